// round 6
// baseline (speedup 1.0000x reference)
#include <cuda_runtime.h>
#include <cuda_bf16.h>

// Problem dims (fixed by the reference)
#define N_TOK   4096
#define C_DIM   768
#define H_NUM   12
#define D_HEAD  64
#define QKV_DIM 2304   // 3*C

// Scratch (device globals: no cudaMalloc allowed)
__device__ float g_qkv[(size_t)N_TOK * QKV_DIM];  // [N, 3C] = [n][{q,k,v} blocks of 768]
__device__ float g_o[(size_t)N_TOK * C_DIM];      // attention output, [n][h*64+d]

// ---------------------------------------------------------------------------
// SGEMM (NT): C[M,N] = A[M,K] * B[N,K]^T + bias[N]
// 128x128 block tile, BK=16, 256 threads, 8x8 micro-tile per thread.
// All dims here are multiples of tile sizes (4096/2304/768), no edge guards.
// ---------------------------------------------------------------------------
__global__ __launch_bounds__(256) void sgemm_nt_bias(
    const float* __restrict__ A, const float* __restrict__ B,
    const float* __restrict__ bias, float* __restrict__ C,
    int M, int N, int K)
{
    __shared__ float As[16][132];   // [k][m], +4 pad
    __shared__ float Bs[16][132];   // [k][n], +4 pad

    const int tid  = threadIdx.x;
    const int m0   = blockIdx.y * 128;
    const int n0   = blockIdx.x * 128;
    const int trow = tid >> 4;      // 0..15
    const int tcol = tid & 15;      // 0..15

    float acc[8][8];
#pragma unroll
    for (int i = 0; i < 8; i++)
#pragma unroll
        for (int j = 0; j < 8; j++) acc[i][j] = 0.0f;

    for (int k0 = 0; k0 < K; k0 += 16) {
#pragma unroll
        for (int i = 0; i < 2; i++) {
            int f   = tid + 256 * i;     // 0..511 float4 slots
            int row = f >> 2;            // 0..127
            int kq  = (f & 3) << 2;      // 0,4,8,12
            float4 av = *(const float4*)&A[(size_t)(m0 + row) * K + k0 + kq];
            As[kq + 0][row] = av.x; As[kq + 1][row] = av.y;
            As[kq + 2][row] = av.z; As[kq + 3][row] = av.w;
            float4 bv = *(const float4*)&B[(size_t)(n0 + row) * K + k0 + kq];
            Bs[kq + 0][row] = bv.x; Bs[kq + 1][row] = bv.y;
            Bs[kq + 2][row] = bv.z; Bs[kq + 3][row] = bv.w;
        }
        __syncthreads();
#pragma unroll
        for (int k = 0; k < 16; k++) {
            float a[8], b[8];
            *(float4*)(a)     = *(const float4*)&As[k][trow * 8];
            *(float4*)(a + 4) = *(const float4*)&As[k][trow * 8 + 4];
            *(float4*)(b)     = *(const float4*)&Bs[k][tcol * 8];
            *(float4*)(b + 4) = *(const float4*)&Bs[k][tcol * 8 + 4];
#pragma unroll
            for (int i = 0; i < 8; i++)
#pragma unroll
                for (int j = 0; j < 8; j++) acc[i][j] += a[i] * b[j];
        }
        __syncthreads();
    }

    float bb[8];
#pragma unroll
    for (int j = 0; j < 8; j++) bb[j] = bias[n0 + tcol * 8 + j];
#pragma unroll
    for (int i = 0; i < 8; i++) {
        float* cp = &C[(size_t)(m0 + trow * 8 + i) * N + n0 + tcol * 8];
        float4 r0 = make_float4(acc[i][0] + bb[0], acc[i][1] + bb[1],
                                acc[i][2] + bb[2], acc[i][3] + bb[3]);
        float4 r1 = make_float4(acc[i][4] + bb[4], acc[i][5] + bb[5],
                                acc[i][6] + bb[6], acc[i][7] + bb[7]);
        *(float4*)(cp)     = r0;
        *(float4*)(cp + 4) = r1;
    }
}

// ---------------------------------------------------------------------------
// Flash attention, fp32, online softmax.
// Grid: (N/64 q-tiles, 12 heads). Block: 256 threads = 8 warps.
// Each warp owns 8 query rows; each lane owns output d-columns {lane, lane+32}.
// Quirk: reference computes softmax(q/D^-0.5 . k) = softmax(8 * q.k);
// the x8 is folded into the Q smem load.
// ---------------------------------------------------------------------------
#define BQ 64
#define BK 64
#define KS_LD 65   // padded row for conflict-free lane-strided reads
// smem floats: Qs 64*64 + Ks 64*65 + Vs 64*64 + Ps 64*64
#define FLASH_SMEM_FLOATS (4096 + 4160 + 4096 + 4096)

__global__ __launch_bounds__(256) void flash_attn_kernel()
{
    extern __shared__ float sm[];
    float* Qs = sm;                 // [q][d]   (x8 pre-scaled)
    float* Ks = sm + 4096;          // [k][d]   row stride 65
    float* Vs = sm + 4096 + 4160;   // [k][d]
    float* Ps = Vs + 4096;          // [wq][k]  per-warp P staging

    const int tid  = threadIdx.x;
    const int w    = tid >> 5;
    const int lane = tid & 31;
    const int q0   = blockIdx.x * BQ;
    const int hoff = blockIdx.y * D_HEAD;

    // Load Q tile, fold the sqrt(D)=8 scale
#pragma unroll
    for (int i = 0; i < 4; i++) {
        int e  = tid + 256 * i;      // float4 slot 0..1023
        int q  = e >> 4;
        int dq = (e & 15) << 2;
        float4 v = *(const float4*)&g_qkv[(size_t)(q0 + q) * QKV_DIM + hoff + dq];
        float* qp = Qs + q * 64 + dq;
        qp[0] = v.x * 8.0f; qp[1] = v.y * 8.0f;
        qp[2] = v.z * 8.0f; qp[3] = v.w * 8.0f;
    }

    float m[8], l[8], o0[8], o1[8];
#pragma unroll
    for (int qi = 0; qi < 8; qi++) {
        m[qi] = -1e30f; l[qi] = 0.0f; o0[qi] = 0.0f; o1[qi] = 0.0f;
    }

    for (int kb = 0; kb < N_TOK; kb += BK) {
        __syncthreads();   // protect Ks/Vs/Ps from previous iteration readers
        // Load K (into padded [k][65]) and V (into [k][64])
#pragma unroll
        for (int i = 0; i < 4; i++) {
            int e  = tid + 256 * i;
            int k  = e >> 4;
            int dq = (e & 15) << 2;
            const float* kp = &g_qkv[(size_t)(kb + k) * QKV_DIM + C_DIM + hoff + dq];
            float4 kv = *(const float4*)kp;
            float* ksp = Ks + k * KS_LD + dq;
            ksp[0] = kv.x; ksp[1] = kv.y; ksp[2] = kv.z; ksp[3] = kv.w;
            float4 vv = *(const float4*)(kp + C_DIM);   // V is +768 past K
            *(float4*)&Vs[k * 64 + dq] = vv;
        }
        __syncthreads();

        // S = Q . K^T   (each lane: 8 q-rows x 2 key cols {lane, lane+32})
        float s0[8], s1[8];
#pragma unroll
        for (int qi = 0; qi < 8; qi++) { s0[qi] = 0.0f; s1[qi] = 0.0f; }
        const float* qb  = Qs + (w * 8) * 64;
        const float* k0p = Ks + lane * KS_LD;
        const float* k1p = Ks + (lane + 32) * KS_LD;
#pragma unroll 2
        for (int d4 = 0; d4 < 64; d4 += 4) {
            float a0[4], a1[4];
#pragma unroll
            for (int i = 0; i < 4; i++) { a0[i] = k0p[d4 + i]; a1[i] = k1p[d4 + i]; }
#pragma unroll
            for (int qi = 0; qi < 8; qi++) {
                float4 qv = *(const float4*)(qb + qi * 64 + d4);
                s0[qi] += qv.x * a0[0] + qv.y * a0[1] + qv.z * a0[2] + qv.w * a0[3];
                s1[qi] += qv.x * a1[0] + qv.y * a1[1] + qv.z * a1[2] + qv.w * a1[3];
            }
        }

        // Online softmax per query row (warp-wide reductions)
#pragma unroll
        for (int qi = 0; qi < 8; qi++) {
            float mx = fmaxf(s0[qi], s1[qi]);
#pragma unroll
            for (int off = 16; off > 0; off >>= 1)
                mx = fmaxf(mx, __shfl_xor_sync(0xffffffffu, mx, off));
            float mnew = fmaxf(m[qi], mx);
            float corr = __expf(m[qi] - mnew);
            float p0 = __expf(s0[qi] - mnew);
            float p1 = __expf(s1[qi] - mnew);
            float ps = p0 + p1;
#pragma unroll
            for (int off = 16; off > 0; off >>= 1)
                ps += __shfl_xor_sync(0xffffffffu, ps, off);
            l[qi] = l[qi] * corr + ps;
            m[qi] = mnew;
            o0[qi] *= corr;
            o1[qi] *= corr;
            Ps[(w * 8 + qi) * 64 + lane]      = p0;
            Ps[(w * 8 + qi) * 64 + lane + 32] = p1;
        }
        __syncwarp();   // Ps writes visible within the warp before PV reads

        // O += P . V  (lane owns d-cols {lane, lane+32})
        const float* pb = Ps + (w * 8) * 64;
#pragma unroll 2
        for (int k4 = 0; k4 < 64; k4 += 4) {
            float v0[4], v1[4];
#pragma unroll
            for (int i = 0; i < 4; i++) {
                v0[i] = Vs[(k4 + i) * 64 + lane];
                v1[i] = Vs[(k4 + i) * 64 + lane + 32];
            }
#pragma unroll
            for (int qi = 0; qi < 8; qi++) {
                float4 pv = *(const float4*)(pb + qi * 64 + k4);
                o0[qi] += pv.x * v0[0] + pv.y * v0[1] + pv.z * v0[2] + pv.w * v0[3];
                o1[qi] += pv.x * v1[0] + pv.y * v1[1] + pv.z * v1[2] + pv.w * v1[3];
            }
        }
    }

    // Normalize and write to g_o[n][h*64+d]  (== transpose(0,2,1,3).reshape)
#pragma unroll
    for (int qi = 0; qi < 8; qi++) {
        float inv = 1.0f / l[qi];
        float* op = g_o + (size_t)(q0 + w * 8 + qi) * C_DIM + hoff;
        op[lane]      = o0[qi] * inv;
        op[lane + 32] = o1[qi] * inv;
    }
}

// ---------------------------------------------------------------------------
// Launch: qkv GEMM -> flash attention -> proj GEMM (default stream, capturable)
// ---------------------------------------------------------------------------
extern "C" void kernel_launch(void* const* d_in, const int* in_sizes, int n_in,
                              void* d_out, int out_size)
{
    (void)in_sizes; (void)n_in; (void)out_size;
    const float* x      = (const float*)d_in[0];
    const float* qkv_w  = (const float*)d_in[1];
    const float* qkv_b  = (const float*)d_in[2];
    const float* proj_w = (const float*)d_in[3];
    const float* proj_b = (const float*)d_in[4];
    float* out = (float*)d_out;

    float* qkv_ptr = nullptr;
    float* o_ptr   = nullptr;
    cudaGetSymbolAddress((void**)&qkv_ptr, g_qkv);
    cudaGetSymbolAddress((void**)&o_ptr,   g_o);

    // 1) qkv[4096,2304] = x[4096,768] @ qkv_w[2304,768]^T + qkv_b
    {
        dim3 grid(QKV_DIM / 128, N_TOK / 128);
        sgemm_nt_bias<<<grid, 256>>>(x, qkv_w, qkv_b, qkv_ptr,
                                     N_TOK, QKV_DIM, C_DIM);
    }
    // 2) flash attention -> g_o[4096,768]
    {
        const int smem = FLASH_SMEM_FLOATS * (int)sizeof(float);  // 65792 B
        cudaFuncSetAttribute(flash_attn_kernel,
                             cudaFuncAttributeMaxDynamicSharedMemorySize, smem);
        dim3 grid(N_TOK / BQ, H_NUM);
        flash_attn_kernel<<<grid, 256, smem>>>();
    }
    // 3) out[4096,768] = g_o @ proj_w[768,768]^T + proj_b
    {
        dim3 grid(C_DIM / 128, N_TOK / 128);
        sgemm_nt_bias<<<grid, 256>>>(o_ptr, proj_w, proj_b, out,
                                     N_TOK, C_DIM, C_DIM);
    }
}

// round 7
// speedup vs baseline: 1.1363x; 1.1363x over previous
#include <cuda_runtime.h>
#include <cuda_bf16.h>

// Problem dims (fixed by the reference)
#define N_TOK   4096
#define C_DIM   768
#define H_NUM   12
#define D_HEAD  64
#define QKV_DIM 2304   // 3*C

// Scratch (device globals: no cudaMalloc allowed)
__device__ float g_qkv[(size_t)N_TOK * QKV_DIM];  // [N, 3C]
__device__ float g_o[(size_t)N_TOK * C_DIM];      // attention output, [n][h*64+d]

// ---------------------------------------------------------------------------
// Packed f32x2 helpers (Blackwell FFMA2 path — ptxas never auto-fuses these)
// b64 register pair: .lo = first float in memory, .hi = second.
// ---------------------------------------------------------------------------
__device__ __forceinline__ void fma2(unsigned long long& d,
                                     unsigned long long a, unsigned long long b) {
    asm("fma.rn.f32x2 %0, %1, %2, %0;" : "+l"(d) : "l"(a), "l"(b));
}
__device__ __forceinline__ void mul2(unsigned long long& d,
                                     unsigned long long a, unsigned long long b) {
    asm("mul.rn.f32x2 %0, %1, %2;" : "=l"(d) : "l"(a), "l"(b));
}
__device__ __forceinline__ unsigned long long dup2(float v) {
    unsigned long long r;
    asm("mov.b64 %0, {%1, %1};" : "=l"(r) : "f"(v));
    return r;
}
__device__ __forceinline__ unsigned long long pack2(float lo, float hi) {
    unsigned long long r;
    asm("mov.b64 %0, {%1, %2};" : "=l"(r) : "f"(lo), "f"(hi));
    return r;
}
__device__ __forceinline__ void unpack2(float& lo, float& hi, unsigned long long v) {
    asm("mov.b64 {%0, %1}, %2;" : "=f"(lo), "=f"(hi) : "l"(v));
}

// ---------------------------------------------------------------------------
// SGEMM (NT): C[M,N] = A[M,K] * B[N,K]^T + bias[N]
// 128x128 block tile, BK=16, 256 threads, 8x8 micro-tile per thread,
// inner product done with packed f32x2 FMAs (acc packed over adjacent n-cols).
// ---------------------------------------------------------------------------
__global__ __launch_bounds__(256) void sgemm_nt_bias(
    const float* __restrict__ A, const float* __restrict__ B,
    const float* __restrict__ bias, float* __restrict__ C,
    int M, int N, int K)
{
    __shared__ __align__(16) float As[16][132];   // [k][m], +4 pad (row 528B, 16B-mult)
    __shared__ __align__(16) float Bs[16][132];   // [k][n]

    const int tid  = threadIdx.x;
    const int m0   = blockIdx.y * 128;
    const int n0   = blockIdx.x * 128;
    const int trow = tid >> 4;      // 0..15
    const int tcol = tid & 15;      // 0..15

    unsigned long long acc2[8][4];  // [m-row][n-pair]
#pragma unroll
    for (int i = 0; i < 8; i++)
#pragma unroll
        for (int j = 0; j < 4; j++) acc2[i][j] = 0ull;

    for (int k0 = 0; k0 < K; k0 += 16) {
#pragma unroll
        for (int i = 0; i < 2; i++) {
            int f   = tid + 256 * i;     // 0..511 float4 slots
            int row = f >> 2;            // 0..127
            int kq  = (f & 3) << 2;      // 0,4,8,12
            float4 av = *(const float4*)&A[(size_t)(m0 + row) * K + k0 + kq];
            As[kq + 0][row] = av.x; As[kq + 1][row] = av.y;
            As[kq + 2][row] = av.z; As[kq + 3][row] = av.w;
            float4 bv = *(const float4*)&B[(size_t)(n0 + row) * K + k0 + kq];
            Bs[kq + 0][row] = bv.x; Bs[kq + 1][row] = bv.y;
            Bs[kq + 2][row] = bv.z; Bs[kq + 3][row] = bv.w;
        }
        __syncthreads();
#pragma unroll
        for (int k = 0; k < 16; k++) {
            float a[8];
            *(float4*)(a)     = *(const float4*)&As[k][trow * 8];
            *(float4*)(a + 4) = *(const float4*)&As[k][trow * 8 + 4];
            ulonglong2 bA = *(const ulonglong2*)&Bs[k][tcol * 8];
            ulonglong2 bB = *(const ulonglong2*)&Bs[k][tcol * 8 + 4];
            unsigned long long b2[4] = {bA.x, bA.y, bB.x, bB.y};
#pragma unroll
            for (int i = 0; i < 8; i++) {
                unsigned long long ad = dup2(a[i]);
                fma2(acc2[i][0], ad, b2[0]);
                fma2(acc2[i][1], ad, b2[1]);
                fma2(acc2[i][2], ad, b2[2]);
                fma2(acc2[i][3], ad, b2[3]);
            }
        }
        __syncthreads();
    }

    float bb[8];
#pragma unroll
    for (int j = 0; j < 8; j++) bb[j] = bias[n0 + tcol * 8 + j];
#pragma unroll
    for (int i = 0; i < 8; i++) {
        float c[8];
#pragma unroll
        for (int j = 0; j < 4; j++) unpack2(c[2 * j], c[2 * j + 1], acc2[i][j]);
        float* cp = &C[(size_t)(m0 + trow * 8 + i) * N + n0 + tcol * 8];
        float4 r0 = make_float4(c[0] + bb[0], c[1] + bb[1], c[2] + bb[2], c[3] + bb[3]);
        float4 r1 = make_float4(c[4] + bb[4], c[5] + bb[5], c[6] + bb[6], c[7] + bb[7]);
        *(float4*)(cp)     = r0;
        *(float4*)(cp + 4) = r1;
    }
}

// ---------------------------------------------------------------------------
// Flash attention, fp32, online softmax, packed-f32x2 math.
// Grid: (N/64 q-tiles, 12 heads). Block: 256 threads = 8 warps.
// Warp owns 8 query rows (as 4 packed q-pairs); lane owns d-cols {lane, lane+32}.
// Q is stored transposed [d][q] and P transposed [k][q] so LDS.128 broadcast
// loads deliver natively-packed q-pairs (zero pack instructions on that side).
// Quirk: reference softmax(q/D^-0.5 . k) = softmax(8*q.k); x8 folded into Q load.
// ---------------------------------------------------------------------------
#define BQ 64
#define BK 64
#define QLD 68   // row stride (floats) for Qs[d][q]: 272B per row -> 16B aligned
#define KLD 65   // Ks[k][d]: conflict-free lane-strided scalar reads
#define PLD 68   // Ps[k][q]: 16B-aligned rows for packed loads
#define OFF_K 4352                 // 64*68
#define OFF_V (OFF_K + 4160)       // 64*65
#define OFF_P (OFF_V + 4096)       // 64*64
#define FLASH_SMEM_FLOATS (OFF_P + 4352)

__global__ __launch_bounds__(256) void flash_attn_kernel()
{
    extern __shared__ __align__(16) float sm[];
    float* Qs = sm;            // [d][q] stride QLD (x8 pre-scaled)
    float* Ks = sm + OFF_K;    // [k][d] stride KLD
    float* Vs = sm + OFF_V;    // [k][64]
    float* Ps = sm + OFF_P;    // [k][q] stride PLD (per-warp column slice)

    const int tid  = threadIdx.x;
    const int w    = tid >> 5;
    const int lane = tid & 31;
    const int q0   = blockIdx.x * BQ;
    const int hoff = blockIdx.y * D_HEAD;

    // Load Q tile transposed, fold the sqrt(D)=8 scale
#pragma unroll
    for (int i = 0; i < 4; i++) {
        int e  = tid + 256 * i;      // float4 slot 0..1023
        int q  = e >> 4;
        int dq = (e & 15) << 2;
        float4 v = *(const float4*)&g_qkv[(size_t)(q0 + q) * QKV_DIM + hoff + dq];
        Qs[(dq + 0) * QLD + q] = v.x * 8.0f;
        Qs[(dq + 1) * QLD + q] = v.y * 8.0f;
        Qs[(dq + 2) * QLD + q] = v.z * 8.0f;
        Qs[(dq + 3) * QLD + q] = v.w * 8.0f;
    }

    unsigned long long o2[4][2];     // [q-pair][d-col], packed over q
    float m[8], l[8];
#pragma unroll
    for (int qp = 0; qp < 4; qp++) { o2[qp][0] = 0ull; o2[qp][1] = 0ull; }
#pragma unroll
    for (int qi = 0; qi < 8; qi++) { m[qi] = -1e30f; l[qi] = 0.0f; }

    for (int kb = 0; kb < N_TOK; kb += BK) {
        __syncthreads();   // protect Ks/Vs from previous iteration readers
#pragma unroll
        for (int i = 0; i < 4; i++) {
            int e  = tid + 256 * i;
            int k  = e >> 4;
            int dq = (e & 15) << 2;
            const float* kp = &g_qkv[(size_t)(kb + k) * QKV_DIM + C_DIM + hoff + dq];
            float4 kv = *(const float4*)kp;
            float* ksp = Ks + k * KLD + dq;
            ksp[0] = kv.x; ksp[1] = kv.y; ksp[2] = kv.z; ksp[3] = kv.w;
            float4 vv = *(const float4*)(kp + C_DIM);   // V is +768 past K
            *(float4*)&Vs[k * 64 + dq] = vv;
        }
        __syncthreads();

        // S = Q . K^T  : acc2[q-pair][key-col], packed over q-pairs
        unsigned long long acc2[4][2];
#pragma unroll
        for (int qp = 0; qp < 4; qp++) { acc2[qp][0] = 0ull; acc2[qp][1] = 0ull; }
        {
            const float* k0p = Ks + lane * KLD;
            const float* k1p = k0p + 32 * KLD;
            const float* qp  = Qs + w * 8;
#pragma unroll 8
            for (int d = 0; d < 64; d++) {
                ulonglong2 qA = *(const ulonglong2*)(qp);      // q-pairs 0,1
                ulonglong2 qB = *(const ulonglong2*)(qp + 4);  // q-pairs 2,3
                unsigned long long k0d = dup2(k0p[d]);
                unsigned long long k1d = dup2(k1p[d]);
                fma2(acc2[0][0], qA.x, k0d); fma2(acc2[0][1], qA.x, k1d);
                fma2(acc2[1][0], qA.y, k0d); fma2(acc2[1][1], qA.y, k1d);
                fma2(acc2[2][0], qB.x, k0d); fma2(acc2[2][1], qB.x, k1d);
                fma2(acc2[3][0], qB.y, k0d); fma2(acc2[3][1], qB.y, k1d);
                qp += QLD;
            }
        }

        // Online softmax per query row
        float s0[8], s1[8], corr[8];
#pragma unroll
        for (int qp = 0; qp < 4; qp++) {
            unpack2(s0[2 * qp], s0[2 * qp + 1], acc2[qp][0]);
            unpack2(s1[2 * qp], s1[2 * qp + 1], acc2[qp][1]);
        }
#pragma unroll
        for (int qi = 0; qi < 8; qi++) {
            float mx = fmaxf(s0[qi], s1[qi]);
#pragma unroll
            for (int off = 16; off > 0; off >>= 1)
                mx = fmaxf(mx, __shfl_xor_sync(0xffffffffu, mx, off));
            float mnew = fmaxf(m[qi], mx);
            corr[qi]   = __expf(m[qi] - mnew);
            float p0 = __expf(s0[qi] - mnew);
            float p1 = __expf(s1[qi] - mnew);
            float ps = p0 + p1;
#pragma unroll
            for (int off = 16; off > 0; off >>= 1)
                ps += __shfl_xor_sync(0xffffffffu, ps, off);
            l[qi] = l[qi] * corr[qi] + ps;
            m[qi] = mnew;
            // P transposed: [k][q]; lane owns k rows {lane, lane+32}
            Ps[lane * PLD + w * 8 + qi]        = p0;
            Ps[(lane + 32) * PLD + w * 8 + qi] = p1;
        }
#pragma unroll
        for (int qp = 0; qp < 4; qp++) {
            unsigned long long c2 = pack2(corr[2 * qp], corr[2 * qp + 1]);
            mul2(o2[qp][0], o2[qp][0], c2);
            mul2(o2[qp][1], o2[qp][1], c2);
        }
        __syncwarp();   // Ps slice is warp-private; warp-scope fence suffices

        // O += P . V  (packed over q-pairs; lane owns d-cols {lane, lane+32})
        {
            const float* pp = Ps + w * 8;
            const float* vp = Vs + lane;
#pragma unroll 8
            for (int k = 0; k < 64; k++) {
                ulonglong2 pA = *(const ulonglong2*)(pp);      // q-pairs 0,1
                ulonglong2 pB = *(const ulonglong2*)(pp + 4);  // q-pairs 2,3
                unsigned long long v0d = dup2(vp[0]);
                unsigned long long v1d = dup2(vp[32]);
                fma2(o2[0][0], pA.x, v0d); fma2(o2[0][1], pA.x, v1d);
                fma2(o2[1][0], pA.y, v0d); fma2(o2[1][1], pA.y, v1d);
                fma2(o2[2][0], pB.x, v0d); fma2(o2[2][1], pB.x, v1d);
                fma2(o2[3][0], pB.y, v0d); fma2(o2[3][1], pB.y, v1d);
                pp += PLD;
                vp += 64;
            }
        }
    }

    // Normalize and write to g_o[n][h*64+d]
#pragma unroll
    for (int qp = 0; qp < 4; qp++) {
        float a, b, c, d;
        unpack2(a, b, o2[qp][0]);   // (q=2qp, q=2qp+1) at col lane
        unpack2(c, d, o2[qp][1]);   // at col lane+32
        float inv0 = 1.0f / l[2 * qp];
        float inv1 = 1.0f / l[2 * qp + 1];
        float* op0 = g_o + (size_t)(q0 + w * 8 + 2 * qp) * C_DIM + hoff;
        float* op1 = op0 + C_DIM;
        op0[lane]      = a * inv0;
        op0[lane + 32] = c * inv0;
        op1[lane]      = b * inv1;
        op1[lane + 32] = d * inv1;
    }
}

// ---------------------------------------------------------------------------
// Launch: qkv GEMM -> flash attention -> proj GEMM (default stream, capturable)
// ---------------------------------------------------------------------------
extern "C" void kernel_launch(void* const* d_in, const int* in_sizes, int n_in,
                              void* d_out, int out_size)
{
    (void)in_sizes; (void)n_in; (void)out_size;
    const float* x      = (const float*)d_in[0];
    const float* qkv_w  = (const float*)d_in[1];
    const float* qkv_b  = (const float*)d_in[2];
    const float* proj_w = (const float*)d_in[3];
    const float* proj_b = (const float*)d_in[4];
    float* out = (float*)d_out;

    float* qkv_ptr = nullptr;
    float* o_ptr   = nullptr;
    cudaGetSymbolAddress((void**)&qkv_ptr, g_qkv);
    cudaGetSymbolAddress((void**)&o_ptr,   g_o);

    // 1) qkv[4096,2304] = x[4096,768] @ qkv_w[2304,768]^T + qkv_b
    {
        dim3 grid(QKV_DIM / 128, N_TOK / 128);
        sgemm_nt_bias<<<grid, 256>>>(x, qkv_w, qkv_b, qkv_ptr,
                                     N_TOK, QKV_DIM, C_DIM);
    }
    // 2) flash attention -> g_o[4096,768]
    {
        const int smem = FLASH_SMEM_FLOATS * (int)sizeof(float);  // 67840 B
        cudaFuncSetAttribute(flash_attn_kernel,
                             cudaFuncAttributeMaxDynamicSharedMemorySize, smem);
        dim3 grid(N_TOK / BQ, H_NUM);
        flash_attn_kernel<<<grid, 256, smem>>>();
    }
    // 3) out[4096,768] = g_o @ proj_w[768,768]^T + proj_b
    {
        dim3 grid(C_DIM / 128, N_TOK / 128);
        sgemm_nt_bias<<<grid, 256>>>(o_ptr, proj_w, proj_b, out,
                                     N_TOK, C_DIM, C_DIM);
    }
}

// round 9
// speedup vs baseline: 1.8483x; 1.6266x over previous
#include <cuda_runtime.h>
#include <cuda_bf16.h>

// Problem dims (fixed by the reference)
#define N_TOK   4096
#define C_DIM   768
#define H_NUM   12
#define D_HEAD  64
#define QKV_DIM 2304   // 3*C

// Scratch (device globals: no cudaMalloc allowed)
__device__ float g_qkv[(size_t)N_TOK * QKV_DIM];  // [N, 3C]
__device__ float g_o[(size_t)N_TOK * C_DIM];      // attention output, [n][h*64+d]

// ---------------------------------------------------------------------------
// Packed f32x2 helpers (for the fp32 SGEMMs)
// ---------------------------------------------------------------------------
__device__ __forceinline__ void fma2(unsigned long long& d,
                                     unsigned long long a, unsigned long long b) {
    asm("fma.rn.f32x2 %0, %1, %2, %0;" : "+l"(d) : "l"(a), "l"(b));
}
__device__ __forceinline__ unsigned long long dup2(float v) {
    unsigned long long r;
    asm("mov.b64 %0, {%1, %1};" : "=l"(r) : "f"(v));
    return r;
}
__device__ __forceinline__ void unpack2(float& lo, float& hi, unsigned long long v) {
    asm("mov.b64 {%0, %1}, %2;" : "=f"(lo), "=f"(hi) : "l"(v));
}

// ---------------------------------------------------------------------------
// bf16 helpers for tensor-core flash attention
// pack_bf16(x, y): bits[0:16) = bf16(x), bits[16:32) = bf16(y)
// ---------------------------------------------------------------------------
__device__ __forceinline__ unsigned pack_bf16(float x, float y) {
    unsigned r;
    asm("cvt.rn.bf16x2.f32 %0, %1, %2;" : "=r"(r) : "f"(y), "f"(x));
    return r;
}
// Dekker split of a float pair into (hi bf16x2, lo bf16x2); x+y exact-ish to 2^-18
__device__ __forceinline__ void split2(float x, float y, unsigned& hi, unsigned& lo) {
    hi = pack_bf16(x, y);
    __nv_bfloat162 h = *reinterpret_cast<__nv_bfloat162*>(&hi);
    lo = pack_bf16(x - __bfloat162float(h.x), y - __bfloat162float(h.y));
}
// m16n8k16 row.col bf16 MMA, fp32 accumulate
__device__ __forceinline__ void mma_bf16(float c[4],
                                         unsigned a0, unsigned a1, unsigned a2, unsigned a3,
                                         unsigned b0, unsigned b1) {
    asm("mma.sync.aligned.m16n8k16.row.col.f32.bf16.bf16.f32 "
        "{%0,%1,%2,%3}, {%4,%5,%6,%7}, {%8,%9}, {%0,%1,%2,%3};"
        : "+f"(c[0]), "+f"(c[1]), "+f"(c[2]), "+f"(c[3])
        : "r"(a0), "r"(a1), "r"(a2), "r"(a3), "r"(b0), "r"(b1));
}

// ---------------------------------------------------------------------------
// SGEMM (NT): C[M,N] = A[M,K] * B[N,K]^T + bias[N]  (fp32, FFMA2) — unchanged
// ---------------------------------------------------------------------------
__global__ __launch_bounds__(256) void sgemm_nt_bias(
    const float* __restrict__ A, const float* __restrict__ B,
    const float* __restrict__ bias, float* __restrict__ C,
    int M, int N, int K)
{
    __shared__ __align__(16) float As[16][132];
    __shared__ __align__(16) float Bs[16][132];

    const int tid  = threadIdx.x;
    const int m0   = blockIdx.y * 128;
    const int n0   = blockIdx.x * 128;
    const int trow = tid >> 4;
    const int tcol = tid & 15;

    unsigned long long acc2[8][4];
#pragma unroll
    for (int i = 0; i < 8; i++)
#pragma unroll
        for (int j = 0; j < 4; j++) acc2[i][j] = 0ull;

    for (int k0 = 0; k0 < K; k0 += 16) {
#pragma unroll
        for (int i = 0; i < 2; i++) {
            int f   = tid + 256 * i;
            int row = f >> 2;
            int kq  = (f & 3) << 2;
            float4 av = *(const float4*)&A[(size_t)(m0 + row) * K + k0 + kq];
            As[kq + 0][row] = av.x; As[kq + 1][row] = av.y;
            As[kq + 2][row] = av.z; As[kq + 3][row] = av.w;
            float4 bv = *(const float4*)&B[(size_t)(n0 + row) * K + k0 + kq];
            Bs[kq + 0][row] = bv.x; Bs[kq + 1][row] = bv.y;
            Bs[kq + 2][row] = bv.z; Bs[kq + 3][row] = bv.w;
        }
        __syncthreads();
#pragma unroll
        for (int k = 0; k < 16; k++) {
            float a[8];
            *(float4*)(a)     = *(const float4*)&As[k][trow * 8];
            *(float4*)(a + 4) = *(const float4*)&As[k][trow * 8 + 4];
            ulonglong2 bA = *(const ulonglong2*)&Bs[k][tcol * 8];
            ulonglong2 bB = *(const ulonglong2*)&Bs[k][tcol * 8 + 4];
            unsigned long long b2[4] = {bA.x, bA.y, bB.x, bB.y};
#pragma unroll
            for (int i = 0; i < 8; i++) {
                unsigned long long ad = dup2(a[i]);
                fma2(acc2[i][0], ad, b2[0]);
                fma2(acc2[i][1], ad, b2[1]);
                fma2(acc2[i][2], ad, b2[2]);
                fma2(acc2[i][3], ad, b2[3]);
            }
        }
        __syncthreads();
    }

    float bb[8];
#pragma unroll
    for (int j = 0; j < 8; j++) bb[j] = bias[n0 + tcol * 8 + j];
#pragma unroll
    for (int i = 0; i < 8; i++) {
        float c[8];
#pragma unroll
        for (int j = 0; j < 4; j++) unpack2(c[2 * j], c[2 * j + 1], acc2[i][j]);
        float* cp = &C[(size_t)(m0 + trow * 8 + i) * N + n0 + tcol * 8];
        float4 r0 = make_float4(c[0] + bb[0], c[1] + bb[1], c[2] + bb[2], c[3] + bb[3]);
        float4 r1 = make_float4(c[4] + bb[4], c[5] + bb[5], c[6] + bb[6], c[7] + bb[7]);
        *(float4*)(cp)     = r0;
        *(float4*)(cp + 4) = r1;
    }
}

// ---------------------------------------------------------------------------
// Flash attention on tensor cores: mma.sync m16n8k16 bf16, 2-term Dekker split
// (hi+lo), 3 MMAs per logical fp32 product => ~2^-18 relative residual.
//
// Grid: (N/128 q-tiles, 12 heads). Block: 256 threads = 8 warps.
// Warp w owns q rows [w*16, w*16+16). BK=64 keys per iteration.
// Layouts:
//   S tile ntile covers keys [8*nt, 8*nt+8); C-frag: thread holds rows
//   (lane/4, lane/4+8), cols (2*(lane%3)... 2*(lane&3), +1).
//   P (C-frag of S) re-packs IN REGISTERS to the A-frag of P·V (FA-2 trick).
//   K smem:  [key][d] as bf16x2 along d, row stride 36 u32 (conflict-free).
//   V smem:  TRANSPOSED [d][key] as bf16 pairs along key, stride 36 u32.
// Quirk: softmax(8 * q.k) — x8 folded into the Q fragments.
// ---------------------------------------------------------------------------
#define BQ 128
#define BK 64
#define KROW 36   // u32 stride per smem row (=> banks 4g+c, all distinct)

__global__ __launch_bounds__(256) void flash_attn_kernel()
{
    __shared__ unsigned Khi[64 * KROW];
    __shared__ unsigned Klo[64 * KROW];
    __shared__ unsigned Vthi[64 * KROW];   // [d][key-pair]
    __shared__ unsigned Vtlo[64 * KROW];

    __nv_bfloat16* Vthi_b = reinterpret_cast<__nv_bfloat16*>(Vthi);
    __nv_bfloat16* Vtlo_b = reinterpret_cast<__nv_bfloat16*>(Vtlo);

    const int tid  = threadIdx.x;
    const int w    = tid >> 5;
    const int lane = tid & 31;
    const int g    = lane >> 2;        // row-in-tile group 0..7
    const int c4   = lane & 3;         // col pair 0..3
    const int q0   = blockIdx.x * BQ;
    const int hoff = blockIdx.y * D_HEAD;

    // --- Q fragments (hi/lo), folded x8 scale. 4 k-chunks over d=64. ---
    unsigned qhi[4][4], qlo[4][4];
    {
        const float* qb = g_qkv + (size_t)(q0 + w * 16 + g) * QKV_DIM + hoff;
        const int d0 = 2 * c4;
#pragma unroll
        for (int kc = 0; kc < 4; kc++) {
            float2 x0 = *(const float2*)(qb + 16 * kc + d0);
            float2 x1 = *(const float2*)(qb + 8 * QKV_DIM + 16 * kc + d0);
            float2 x2 = *(const float2*)(qb + 16 * kc + d0 + 8);
            float2 x3 = *(const float2*)(qb + 8 * QKV_DIM + 16 * kc + d0 + 8);
            split2(x0.x * 8.0f, x0.y * 8.0f, qhi[kc][0], qlo[kc][0]);
            split2(x1.x * 8.0f, x1.y * 8.0f, qhi[kc][1], qlo[kc][1]);
            split2(x2.x * 8.0f, x2.y * 8.0f, qhi[kc][2], qlo[kc][2]);
            split2(x3.x * 8.0f, x3.y * 8.0f, qhi[kc][3], qlo[kc][3]);
        }
    }

    float o[8][4];                 // O accumulators: 8 d-tiles x C-frag
    float m0r = -1e30f, m1r = -1e30f, l0r = 0.0f, l1r = 0.0f;
#pragma unroll
    for (int t = 0; t < 8; t++)
#pragma unroll
        for (int j = 0; j < 4; j++) o[t][j] = 0.0f;

    for (int kb = 0; kb < N_TOK; kb += BK) {
        __syncthreads();   // previous iteration's readers done
        // --- Stage K (hi/lo bf16x2 along d) and V transposed ---
#pragma unroll
        for (int i = 0; i < 4; i++) {
            int e   = tid + 256 * i;
            int key = e >> 4;
            int dq  = (e & 15) << 2;
            const float* kp = &g_qkv[(size_t)(kb + key) * QKV_DIM + C_DIM + hoff + dq];
            float4 kv = *(const float4*)kp;
            unsigned h0, l0, h1, l1;
            split2(kv.x, kv.y, h0, l0);
            split2(kv.z, kv.w, h1, l1);
            Khi[key * KROW + (dq >> 1)]     = h0;
            Khi[key * KROW + (dq >> 1) + 1] = h1;
            Klo[key * KROW + (dq >> 1)]     = l0;
            Klo[key * KROW + (dq >> 1) + 1] = l1;
            float4 vv = *(const float4*)(kp + C_DIM);   // V is +768 past K
            float vals[4] = {vv.x, vv.y, vv.z, vv.w};
#pragma unroll
            for (int j = 0; j < 4; j++) {
                __nv_bfloat16 vh = __float2bfloat16_rn(vals[j]);
                Vthi_b[(dq + j) * (2 * KROW) + key] = vh;
                Vtlo_b[(dq + j) * (2 * KROW) + key] =
                    __float2bfloat16_rn(vals[j] - __bfloat162float(vh));
            }
        }
        __syncthreads();

        // --- S = Q . K^T : 8 n-tiles (8 keys each), 3-term split ---
        float s[8][4];
#pragma unroll
        for (int t = 0; t < 8; t++) {
#pragma unroll
            for (int j = 0; j < 4; j++) s[t][j] = 0.0f;
            const int brow = (t * 8 + g) * KROW;
#pragma unroll
            for (int kc = 0; kc < 4; kc++) {
                unsigned bh0 = Khi[brow + kc * 8 + c4];
                unsigned bh1 = Khi[brow + kc * 8 + c4 + 4];
                unsigned bl0 = Klo[brow + kc * 8 + c4];
                unsigned bl1 = Klo[brow + kc * 8 + c4 + 4];
                mma_bf16(s[t], qhi[kc][0], qhi[kc][1], qhi[kc][2], qhi[kc][3], bh0, bh1);
                mma_bf16(s[t], qhi[kc][0], qhi[kc][1], qhi[kc][2], qhi[kc][3], bl0, bl1);
                mma_bf16(s[t], qlo[kc][0], qlo[kc][1], qlo[kc][2], qlo[kc][3], bh0, bh1);
            }
        }

        // --- Online softmax (rows g and g+8; quad shuffles xor 1,2) ---
        float mx0 = -1e30f, mx1 = -1e30f;
#pragma unroll
        for (int t = 0; t < 8; t++) {
            mx0 = fmaxf(mx0, fmaxf(s[t][0], s[t][1]));
            mx1 = fmaxf(mx1, fmaxf(s[t][2], s[t][3]));
        }
        mx0 = fmaxf(mx0, __shfl_xor_sync(0xffffffffu, mx0, 1));
        mx0 = fmaxf(mx0, __shfl_xor_sync(0xffffffffu, mx0, 2));
        mx1 = fmaxf(mx1, __shfl_xor_sync(0xffffffffu, mx1, 1));
        mx1 = fmaxf(mx1, __shfl_xor_sync(0xffffffffu, mx1, 2));
        float mn0 = fmaxf(m0r, mx0), mn1 = fmaxf(m1r, mx1);
        float cr0 = __expf(m0r - mn0), cr1 = __expf(m1r - mn1);
        m0r = mn0; m1r = mn1;
        float ps0 = 0.0f, ps1 = 0.0f;
#pragma unroll
        for (int t = 0; t < 8; t++) {
            s[t][0] = __expf(s[t][0] - mn0);
            s[t][1] = __expf(s[t][1] - mn0);
            s[t][2] = __expf(s[t][2] - mn1);
            s[t][3] = __expf(s[t][3] - mn1);
            ps0 += s[t][0] + s[t][1];
            ps1 += s[t][2] + s[t][3];
        }
        ps0 += __shfl_xor_sync(0xffffffffu, ps0, 1);
        ps0 += __shfl_xor_sync(0xffffffffu, ps0, 2);
        ps1 += __shfl_xor_sync(0xffffffffu, ps1, 1);
        ps1 += __shfl_xor_sync(0xffffffffu, ps1, 2);
        l0r = l0r * cr0 + ps0;
        l1r = l1r * cr1 + ps1;
#pragma unroll
        for (int t = 0; t < 8; t++) {
            o[t][0] *= cr0; o[t][1] *= cr0;
            o[t][2] *= cr1; o[t][3] *= cr1;
        }

        // --- P fragments (hi/lo) from S C-frags: FA-2 in-register repack ---
        unsigned phi[4][4], plo[4][4];
#pragma unroll
        for (int kc = 0; kc < 4; kc++) {
            split2(s[2 * kc][0],     s[2 * kc][1],     phi[kc][0], plo[kc][0]);
            split2(s[2 * kc][2],     s[2 * kc][3],     phi[kc][1], plo[kc][1]);
            split2(s[2 * kc + 1][0], s[2 * kc + 1][1], phi[kc][2], plo[kc][2]);
            split2(s[2 * kc + 1][2], s[2 * kc + 1][3], phi[kc][3], plo[kc][3]);
        }

        // --- O += P . V : 8 d-tiles, 3-term split (PhiVhi + PhiVlo + PloVhi) ---
#pragma unroll
        for (int t = 0; t < 8; t++) {
            const int brow = (t * 8 + g) * KROW;
#pragma unroll
            for (int kc = 0; kc < 4; kc++) {
                unsigned bh0 = Vthi[brow + kc * 8 + c4];
                unsigned bh1 = Vthi[brow + kc * 8 + c4 + 4];
                unsigned bl0 = Vtlo[brow + kc * 8 + c4];
                unsigned bl1 = Vtlo[brow + kc * 8 + c4 + 4];
                mma_bf16(o[t], phi[kc][0], phi[kc][1], phi[kc][2], phi[kc][3], bh0, bh1);
                mma_bf16(o[t], phi[kc][0], phi[kc][1], phi[kc][2], phi[kc][3], bl0, bl1);
                mma_bf16(o[t], plo[kc][0], plo[kc][1], plo[kc][2], plo[kc][3], bh0, bh1);
            }
        }
    }

    // --- Normalize, write O (row r, col 8t+2c4{,+1}) to g_o[n][h*64+d] ---
    float inv0 = 1.0f / l0r, inv1 = 1.0f / l1r;
    float* op0 = g_o + (size_t)(q0 + w * 16 + g) * C_DIM + hoff;
    float* op1 = op0 + 8 * C_DIM;
#pragma unroll
    for (int t = 0; t < 8; t++) {
        *(float2*)(op0 + t * 8 + 2 * c4) = make_float2(o[t][0] * inv0, o[t][1] * inv0);
        *(float2*)(op1 + t * 8 + 2 * c4) = make_float2(o[t][2] * inv1, o[t][3] * inv1);
    }
}

// ---------------------------------------------------------------------------
// Launch: qkv GEMM -> flash attention (tensor cores) -> proj GEMM
// ---------------------------------------------------------------------------
extern "C" void kernel_launch(void* const* d_in, const int* in_sizes, int n_in,
                              void* d_out, int out_size)
{
    (void)in_sizes; (void)n_in; (void)out_size;
    const float* x      = (const float*)d_in[0];
    const float* qkv_w  = (const float*)d_in[1];
    const float* qkv_b  = (const float*)d_in[2];
    const float* proj_w = (const float*)d_in[3];
    const float* proj_b = (const float*)d_in[4];
    float* out = (float*)d_out;

    float* qkv_ptr = nullptr;
    float* o_ptr   = nullptr;
    cudaGetSymbolAddress((void**)&qkv_ptr, g_qkv);
    cudaGetSymbolAddress((void**)&o_ptr,   g_o);

    // 1) qkv[4096,2304] = x[4096,768] @ qkv_w[2304,768]^T + qkv_b
    {
        dim3 grid(QKV_DIM / 128, N_TOK / 128);
        sgemm_nt_bias<<<grid, 256>>>(x, qkv_w, qkv_b, qkv_ptr,
                                     N_TOK, QKV_DIM, C_DIM);
    }
    // 2) flash attention (tensor cores) -> g_o[4096,768]
    {
        dim3 grid(N_TOK / BQ, H_NUM);
        flash_attn_kernel<<<grid, 256>>>();
    }
    // 3) out[4096,768] = g_o @ proj_w[768,768]^T + proj_b
    {
        dim3 grid(C_DIM / 128, N_TOK / 128);
        sgemm_nt_bias<<<grid, 256>>>(o_ptr, proj_w, proj_b, out,
                                     N_TOK, C_DIM, C_DIM);
    }
}

// round 14
// speedup vs baseline: 2.2104x; 1.1959x over previous
#include <cuda_runtime.h>
#include <cuda_bf16.h>

// Problem dims (fixed by the reference)
#define N_TOK   4096
#define C_DIM   768
#define H_NUM   12
#define D_HEAD  64
#define QKV_DIM 2304   // 3*C

// Scratch (device globals: no cudaMalloc allowed)
__device__ float g_qkv[(size_t)N_TOK * QKV_DIM];  // [N, 3C]
__device__ float g_o[(size_t)N_TOK * C_DIM];      // attention output, [n][h*64+d]

// ---------------------------------------------------------------------------
// bf16 helpers: pack_bf16(x, y) -> bits[0:16)=bf16(x), bits[16:32)=bf16(y)
// ---------------------------------------------------------------------------
__device__ __forceinline__ unsigned pack_bf16(float x, float y) {
    unsigned r;
    asm("cvt.rn.bf16x2.f32 %0, %1, %2;" : "=r"(r) : "f"(y), "f"(x));
    return r;
}
// Dekker split of a float pair into (hi bf16x2, lo bf16x2); residual ~2^-18
__device__ __forceinline__ void split2(float x, float y, unsigned& hi, unsigned& lo) {
    hi = pack_bf16(x, y);
    __nv_bfloat162 h = *reinterpret_cast<__nv_bfloat162*>(&hi);
    lo = pack_bf16(x - __bfloat162float(h.x), y - __bfloat162float(h.y));
}
// m16n8k16 row.col bf16 MMA, fp32 accumulate
__device__ __forceinline__ void mma_bf16(float c[4],
                                         unsigned a0, unsigned a1, unsigned a2, unsigned a3,
                                         unsigned b0, unsigned b1) {
    asm("mma.sync.aligned.m16n8k16.row.col.f32.bf16.bf16.f32 "
        "{%0,%1,%2,%3}, {%4,%5,%6,%7}, {%8,%9}, {%0,%1,%2,%3};"
        : "+f"(c[0]), "+f"(c[1]), "+f"(c[2]), "+f"(c[3])
        : "r"(a0), "r"(a1), "r"(a2), "r"(a3), "r"(b0), "r"(b1));
}

// ---------------------------------------------------------------------------
// Tensor-core GEMM (NT): C[M,N] = A[M,K]*B[N,K]^T + bias[N]
// bf16 Dekker split (3 MMAs per logical fp32 product), fp32 accumulate.
// 128x128 CTA tile, BK=32, 256 threads = 8 warps as 4(m) x 2(n);
// warp tile m32 x n64 = 2 m16-tiles x 8 n8-tiles.
// smem: hi/lo bf16x2 arrays, row stride 18 u32 (16-u32 payload) ->
// fragment loads hit banks (18g + c4) % 32, all 32 distinct.
// ---------------------------------------------------------------------------
#define GS 18   // u32 row stride in staged smem

__global__ __launch_bounds__(256) void gemm_bf16s_nt_bias(
    const float* __restrict__ A, const float* __restrict__ B,
    const float* __restrict__ bias, float* __restrict__ C,
    int M, int N, int K)
{
    __shared__ unsigned Ahi[128 * GS], Alo[128 * GS];
    __shared__ unsigned Bhi[128 * GS], Blo[128 * GS];

    const int tid  = threadIdx.x;
    const int w    = tid >> 5;
    const int lane = tid & 31;
    const int g    = lane >> 2;
    const int c4   = lane & 3;
    const int wm   = w >> 1;        // 0..3
    const int wn   = w & 1;         // 0..1
    const int m0   = blockIdx.y * 128;
    const int n0   = blockIdx.x * 128;

    float acc[2][8][4];
#pragma unroll
    for (int tm = 0; tm < 2; tm++)
#pragma unroll
        for (int tn = 0; tn < 8; tn++)
#pragma unroll
            for (int j = 0; j < 4; j++) acc[tm][tn][j] = 0.0f;

    for (int k0 = 0; k0 < K; k0 += 32) {
        __syncthreads();
        // Stage A and B tiles as hi/lo bf16x2 (each thread: 4 float4 per tensor)
#pragma unroll
        for (int i = 0; i < 4; i++) {
            int f   = tid + 256 * i;       // 0..1023 float4 slots
            int row = f >> 3;              // 0..127
            int kq  = (f & 7) << 2;        // 0,4,...,28
            unsigned h0, l0, h1, l1;
            float4 av = *(const float4*)&A[(size_t)(m0 + row) * K + k0 + kq];
            split2(av.x, av.y, h0, l0);
            split2(av.z, av.w, h1, l1);
            Ahi[row * GS + (kq >> 1)]     = h0;
            Ahi[row * GS + (kq >> 1) + 1] = h1;
            Alo[row * GS + (kq >> 1)]     = l0;
            Alo[row * GS + (kq >> 1) + 1] = l1;
            float4 bv = *(const float4*)&B[(size_t)(n0 + row) * K + k0 + kq];
            split2(bv.x, bv.y, h0, l0);
            split2(bv.z, bv.w, h1, l1);
            Bhi[row * GS + (kq >> 1)]     = h0;
            Bhi[row * GS + (kq >> 1) + 1] = h1;
            Blo[row * GS + (kq >> 1)]     = l0;
            Blo[row * GS + (kq >> 1) + 1] = l1;
        }
        __syncthreads();

#pragma unroll
        for (int kc = 0; kc < 2; kc++) {
            // A fragments (hi/lo) for 2 m16 tiles
            unsigned ah[2][4], al[2][4];
#pragma unroll
            for (int tm = 0; tm < 2; tm++) {
                int r = (wm * 32 + tm * 16 + g) * GS + kc * 8 + c4;
                ah[tm][0] = Ahi[r];
                ah[tm][1] = Ahi[r + 8 * GS];
                ah[tm][2] = Ahi[r + 4];
                ah[tm][3] = Ahi[r + 8 * GS + 4];
                al[tm][0] = Alo[r];
                al[tm][1] = Alo[r + 8 * GS];
                al[tm][2] = Alo[r + 4];
                al[tm][3] = Alo[r + 8 * GS + 4];
            }
#pragma unroll
            for (int tn = 0; tn < 8; tn++) {
                int rb = (wn * 64 + tn * 8 + g) * GS + kc * 8 + c4;
                unsigned bh0 = Bhi[rb],     bh1 = Bhi[rb + 4];
                unsigned bl0 = Blo[rb],     bl1 = Blo[rb + 4];
#pragma unroll
                for (int tm = 0; tm < 2; tm++) {
                    mma_bf16(acc[tm][tn], ah[tm][0], ah[tm][1], ah[tm][2], ah[tm][3], bh0, bh1);
                    mma_bf16(acc[tm][tn], ah[tm][0], ah[tm][1], ah[tm][2], ah[tm][3], bl0, bl1);
                    mma_bf16(acc[tm][tn], al[tm][0], al[tm][1], al[tm][2], al[tm][3], bh0, bh1);
                }
            }
        }
    }

    // Epilogue: add bias, write float2 per (tile, row-half)
#pragma unroll
    for (int tm = 0; tm < 2; tm++) {
        int r0 = m0 + wm * 32 + tm * 16 + g;
#pragma unroll
        for (int tn = 0; tn < 8; tn++) {
            int col = n0 + wn * 64 + tn * 8 + 2 * c4;
            float2 bb = *(const float2*)&bias[col];
            float* cp0 = &C[(size_t)r0 * N + col];
            float* cp1 = cp0 + 8 * (size_t)N;
            *(float2*)cp0 = make_float2(acc[tm][tn][0] + bb.x, acc[tm][tn][1] + bb.y);
            *(float2*)cp1 = make_float2(acc[tm][tn][2] + bb.x, acc[tm][tn][3] + bb.y);
        }
    }
}

// ---------------------------------------------------------------------------
// Flash attention on tensor cores (unchanged from R8): mma.sync m16n8k16 bf16,
// 2-term Dekker split, 3 MMAs per logical product, FA-2 in-register P repack.
// Grid: (N/128 q-tiles, 12 heads). Block: 256 threads = 8 warps.
// Quirk: softmax(8 * q.k) — x8 folded into the Q fragments.
// ---------------------------------------------------------------------------
#define BQ 128
#define BK 64
#define KROW 36   // u32 stride per smem row (=> banks 4g+c, all distinct)

__global__ __launch_bounds__(256) void flash_attn_kernel()
{
    __shared__ unsigned Khi[64 * KROW];
    __shared__ unsigned Klo[64 * KROW];
    __shared__ unsigned Vthi[64 * KROW];   // [d][key-pair]
    __shared__ unsigned Vtlo[64 * KROW];

    __nv_bfloat16* Vthi_b = reinterpret_cast<__nv_bfloat16*>(Vthi);
    __nv_bfloat16* Vtlo_b = reinterpret_cast<__nv_bfloat16*>(Vtlo);

    const int tid  = threadIdx.x;
    const int w    = tid >> 5;
    const int lane = tid & 31;
    const int g    = lane >> 2;        // row-in-tile group 0..7
    const int c4   = lane & 3;         // col pair 0..3
    const int q0   = blockIdx.x * BQ;
    const int hoff = blockIdx.y * D_HEAD;

    // --- Q fragments (hi/lo), folded x8 scale. 4 k-chunks over d=64. ---
    unsigned qhi[4][4], qlo[4][4];
    {
        const float* qb = g_qkv + (size_t)(q0 + w * 16 + g) * QKV_DIM + hoff;
        const int d0 = 2 * c4;
#pragma unroll
        for (int kc = 0; kc < 4; kc++) {
            float2 x0 = *(const float2*)(qb + 16 * kc + d0);
            float2 x1 = *(const float2*)(qb + 8 * QKV_DIM + 16 * kc + d0);
            float2 x2 = *(const float2*)(qb + 16 * kc + d0 + 8);
            float2 x3 = *(const float2*)(qb + 8 * QKV_DIM + 16 * kc + d0 + 8);
            split2(x0.x * 8.0f, x0.y * 8.0f, qhi[kc][0], qlo[kc][0]);
            split2(x1.x * 8.0f, x1.y * 8.0f, qhi[kc][1], qlo[kc][1]);
            split2(x2.x * 8.0f, x2.y * 8.0f, qhi[kc][2], qlo[kc][2]);
            split2(x3.x * 8.0f, x3.y * 8.0f, qhi[kc][3], qlo[kc][3]);
        }
    }

    float o[8][4];                 // O accumulators: 8 d-tiles x C-frag
    float m0r = -1e30f, m1r = -1e30f, l0r = 0.0f, l1r = 0.0f;
#pragma unroll
    for (int t = 0; t < 8; t++)
#pragma unroll
        for (int j = 0; j < 4; j++) o[t][j] = 0.0f;

    for (int kb = 0; kb < N_TOK; kb += BK) {
        __syncthreads();   // previous iteration's readers done
        // --- Stage K (hi/lo bf16x2 along d) and V transposed ---
#pragma unroll
        for (int i = 0; i < 4; i++) {
            int e   = tid + 256 * i;
            int key = e >> 4;
            int dq  = (e & 15) << 2;
            const float* kp = &g_qkv[(size_t)(kb + key) * QKV_DIM + C_DIM + hoff + dq];
            float4 kv = *(const float4*)kp;
            unsigned h0, l0, h1, l1;
            split2(kv.x, kv.y, h0, l0);
            split2(kv.z, kv.w, h1, l1);
            Khi[key * KROW + (dq >> 1)]     = h0;
            Khi[key * KROW + (dq >> 1) + 1] = h1;
            Klo[key * KROW + (dq >> 1)]     = l0;
            Klo[key * KROW + (dq >> 1) + 1] = l1;
            float4 vv = *(const float4*)(kp + C_DIM);   // V is +768 past K
            float vals[4] = {vv.x, vv.y, vv.z, vv.w};
#pragma unroll
            for (int j = 0; j < 4; j++) {
                __nv_bfloat16 vh = __float2bfloat16_rn(vals[j]);
                Vthi_b[(dq + j) * (2 * KROW) + key] = vh;
                Vtlo_b[(dq + j) * (2 * KROW) + key] =
                    __float2bfloat16_rn(vals[j] - __bfloat162float(vh));
            }
        }
        __syncthreads();

        // --- S = Q . K^T : 8 n-tiles (8 keys each), 3-term split ---
        float s[8][4];
#pragma unroll
        for (int t = 0; t < 8; t++) {
#pragma unroll
            for (int j = 0; j < 4; j++) s[t][j] = 0.0f;
            const int brow = (t * 8 + g) * KROW;
#pragma unroll
            for (int kc = 0; kc < 4; kc++) {
                unsigned bh0 = Khi[brow + kc * 8 + c4];
                unsigned bh1 = Khi[brow + kc * 8 + c4 + 4];
                unsigned bl0 = Klo[brow + kc * 8 + c4];
                unsigned bl1 = Klo[brow + kc * 8 + c4 + 4];
                mma_bf16(s[t], qhi[kc][0], qhi[kc][1], qhi[kc][2], qhi[kc][3], bh0, bh1);
                mma_bf16(s[t], qhi[kc][0], qhi[kc][1], qhi[kc][2], qhi[kc][3], bl0, bl1);
                mma_bf16(s[t], qlo[kc][0], qlo[kc][1], qlo[kc][2], qlo[kc][3], bh0, bh1);
            }
        }

        // --- Online softmax (rows g and g+8; quad shuffles xor 1,2) ---
        float mx0 = -1e30f, mx1 = -1e30f;
#pragma unroll
        for (int t = 0; t < 8; t++) {
            mx0 = fmaxf(mx0, fmaxf(s[t][0], s[t][1]));
            mx1 = fmaxf(mx1, fmaxf(s[t][2], s[t][3]));
        }
        mx0 = fmaxf(mx0, __shfl_xor_sync(0xffffffffu, mx0, 1));
        mx0 = fmaxf(mx0, __shfl_xor_sync(0xffffffffu, mx0, 2));
        mx1 = fmaxf(mx1, __shfl_xor_sync(0xffffffffu, mx1, 1));
        mx1 = fmaxf(mx1, __shfl_xor_sync(0xffffffffu, mx1, 2));
        float mn0 = fmaxf(m0r, mx0), mn1 = fmaxf(m1r, mx1);
        float cr0 = __expf(m0r - mn0), cr1 = __expf(m1r - mn1);
        m0r = mn0; m1r = mn1;
        float ps0 = 0.0f, ps1 = 0.0f;
#pragma unroll
        for (int t = 0; t < 8; t++) {
            s[t][0] = __expf(s[t][0] - mn0);
            s[t][1] = __expf(s[t][1] - mn0);
            s[t][2] = __expf(s[t][2] - mn1);
            s[t][3] = __expf(s[t][3] - mn1);
            ps0 += s[t][0] + s[t][1];
            ps1 += s[t][2] + s[t][3];
        }
        ps0 += __shfl_xor_sync(0xffffffffu, ps0, 1);
        ps0 += __shfl_xor_sync(0xffffffffu, ps0, 2);
        ps1 += __shfl_xor_sync(0xffffffffu, ps1, 1);
        ps1 += __shfl_xor_sync(0xffffffffu, ps1, 2);
        l0r = l0r * cr0 + ps0;
        l1r = l1r * cr1 + ps1;
#pragma unroll
        for (int t = 0; t < 8; t++) {
            o[t][0] *= cr0; o[t][1] *= cr0;
            o[t][2] *= cr1; o[t][3] *= cr1;
        }

        // --- P fragments (hi/lo) from S C-frags: FA-2 in-register repack ---
        unsigned phi[4][4], plo[4][4];
#pragma unroll
        for (int kc = 0; kc < 4; kc++) {
            split2(s[2 * kc][0],     s[2 * kc][1],     phi[kc][0], plo[kc][0]);
            split2(s[2 * kc][2],     s[2 * kc][3],     phi[kc][1], plo[kc][1]);
            split2(s[2 * kc + 1][0], s[2 * kc + 1][1], phi[kc][2], plo[kc][2]);
            split2(s[2 * kc + 1][2], s[2 * kc + 1][3], phi[kc][3], plo[kc][3]);
        }

        // --- O += P . V : 8 d-tiles, 3-term split ---
#pragma unroll
        for (int t = 0; t < 8; t++) {
            const int brow = (t * 8 + g) * KROW;
#pragma unroll
            for (int kc = 0; kc < 4; kc++) {
                unsigned bh0 = Vthi[brow + kc * 8 + c4];
                unsigned bh1 = Vthi[brow + kc * 8 + c4 + 4];
                unsigned bl0 = Vtlo[brow + kc * 8 + c4];
                unsigned bl1 = Vtlo[brow + kc * 8 + c4 + 4];
                mma_bf16(o[t], phi[kc][0], phi[kc][1], phi[kc][2], phi[kc][3], bh0, bh1);
                mma_bf16(o[t], phi[kc][0], phi[kc][1], phi[kc][2], phi[kc][3], bl0, bl1);
                mma_bf16(o[t], plo[kc][0], plo[kc][1], plo[kc][2], plo[kc][3], bh0, bh1);
            }
        }
    }

    // --- Normalize, write O to g_o[n][h*64+d] ---
    float inv0 = 1.0f / l0r, inv1 = 1.0f / l1r;
    float* op0 = g_o + (size_t)(q0 + w * 16 + g) * C_DIM + hoff;
    float* op1 = op0 + 8 * C_DIM;
#pragma unroll
    for (int t = 0; t < 8; t++) {
        *(float2*)(op0 + t * 8 + 2 * c4) = make_float2(o[t][0] * inv0, o[t][1] * inv0);
        *(float2*)(op1 + t * 8 + 2 * c4) = make_float2(o[t][2] * inv1, o[t][3] * inv1);
    }
}

// ---------------------------------------------------------------------------
// Launch: qkv GEMM -> flash attention -> proj GEMM (all tensor-core now)
// ---------------------------------------------------------------------------
extern "C" void kernel_launch(void* const* d_in, const int* in_sizes, int n_in,
                              void* d_out, int out_size)
{
    (void)in_sizes; (void)n_in; (void)out_size;
    const float* x      = (const float*)d_in[0];
    const float* qkv_w  = (const float*)d_in[1];
    const float* qkv_b  = (const float*)d_in[2];
    const float* proj_w = (const float*)d_in[3];
    const float* proj_b = (const float*)d_in[4];
    float* out = (float*)d_out;

    float* qkv_ptr = nullptr;
    float* o_ptr   = nullptr;
    cudaGetSymbolAddress((void**)&qkv_ptr, g_qkv);
    cudaGetSymbolAddress((void**)&o_ptr,   g_o);

    // 1) qkv[4096,2304] = x[4096,768] @ qkv_w[2304,768]^T + qkv_b
    {
        dim3 grid(QKV_DIM / 128, N_TOK / 128);
        gemm_bf16s_nt_bias<<<grid, 256>>>(x, qkv_w, qkv_b, qkv_ptr,
                                          N_TOK, QKV_DIM, C_DIM);
    }
    // 2) flash attention (tensor cores) -> g_o[4096,768]
    {
        dim3 grid(N_TOK / BQ, H_NUM);
        flash_attn_kernel<<<grid, 256>>>();
    }
    // 3) out[4096,768] = g_o @ proj_w[768,768]^T + proj_b
    {
        dim3 grid(C_DIM / 128, N_TOK / 128);
        gemm_bf16s_nt_bias<<<grid, 256>>>(o_ptr, proj_w, proj_b, out,
                                          N_TOK, C_DIM, C_DIM);
    }
}

// round 17
// speedup vs baseline: 2.7897x; 1.2621x over previous
#include <cuda_runtime.h>
#include <cuda_bf16.h>

// Problem dims (fixed by the reference)
#define N_TOK   4096
#define C_DIM   768
#define H_NUM   12
#define D_HEAD  64
#define QKV_DIM 2304   // 3*C

// Scratch (device globals: no cudaMalloc allowed)
__device__ float g_qkv[(size_t)N_TOK * QKV_DIM];  // [N, 3C]
__device__ float g_o[(size_t)N_TOK * C_DIM];      // attention output, [n][h*64+d]

// Pre-split K/V (bf16 Dekker hi/lo), written once by split_kv_kernel:
//   g_khi/g_klo : [h][key][d-pair]  u32 = bf16x2 along d, 32 u32 per key row
//   g_vthi/g_vtlo: [h][d][key-pair] u32 = bf16x2 along key, 2048 u32 per d row
__device__ unsigned g_khi [(size_t)H_NUM * N_TOK * 32];
__device__ unsigned g_klo [(size_t)H_NUM * N_TOK * 32];
__device__ unsigned g_vthi[(size_t)H_NUM * D_HEAD * (N_TOK / 2)];
__device__ unsigned g_vtlo[(size_t)H_NUM * D_HEAD * (N_TOK / 2)];

// ---------------------------------------------------------------------------
// bf16 helpers: pack_bf16(x, y) -> bits[0:16)=bf16(x), bits[16:32)=bf16(y)
// ---------------------------------------------------------------------------
__device__ __forceinline__ unsigned pack_bf16(float x, float y) {
    unsigned r;
    asm("cvt.rn.bf16x2.f32 %0, %1, %2;" : "=r"(r) : "f"(y), "f"(x));
    return r;
}
// Dekker split of a float pair into (hi bf16x2, lo bf16x2); residual ~2^-18
__device__ __forceinline__ void split2(float x, float y, unsigned& hi, unsigned& lo) {
    hi = pack_bf16(x, y);
    __nv_bfloat162 h = *reinterpret_cast<__nv_bfloat162*>(&hi);
    lo = pack_bf16(x - __bfloat162float(h.x), y - __bfloat162float(h.y));
}
// m16n8k16 row.col bf16 MMA, fp32 accumulate
__device__ __forceinline__ void mma_bf16(float c[4],
                                         unsigned a0, unsigned a1, unsigned a2, unsigned a3,
                                         unsigned b0, unsigned b1) {
    asm("mma.sync.aligned.m16n8k16.row.col.f32.bf16.bf16.f32 "
        "{%0,%1,%2,%3}, {%4,%5,%6,%7}, {%8,%9}, {%0,%1,%2,%3};"
        : "+f"(c[0]), "+f"(c[1]), "+f"(c[2]), "+f"(c[3])
        : "r"(a0), "r"(a1), "r"(a2), "r"(a3), "r"(b0), "r"(b1));
}

// ---------------------------------------------------------------------------
// Tensor-core GEMM (NT): C[M,N] = A[M,K]*B[N,K]^T + bias[N]  (unchanged R14)
// ---------------------------------------------------------------------------
#define GS 18   // u32 row stride in staged smem

__global__ __launch_bounds__(256) void gemm_bf16s_nt_bias(
    const float* __restrict__ A, const float* __restrict__ B,
    const float* __restrict__ bias, float* __restrict__ C,
    int M, int N, int K)
{
    __shared__ unsigned Ahi[128 * GS], Alo[128 * GS];
    __shared__ unsigned Bhi[128 * GS], Blo[128 * GS];

    const int tid  = threadIdx.x;
    const int w    = tid >> 5;
    const int lane = tid & 31;
    const int g    = lane >> 2;
    const int c4   = lane & 3;
    const int wm   = w >> 1;
    const int wn   = w & 1;
    const int m0   = blockIdx.y * 128;
    const int n0   = blockIdx.x * 128;

    float acc[2][8][4];
#pragma unroll
    for (int tm = 0; tm < 2; tm++)
#pragma unroll
        for (int tn = 0; tn < 8; tn++)
#pragma unroll
            for (int j = 0; j < 4; j++) acc[tm][tn][j] = 0.0f;

    for (int k0 = 0; k0 < K; k0 += 32) {
        __syncthreads();
#pragma unroll
        for (int i = 0; i < 4; i++) {
            int f   = tid + 256 * i;
            int row = f >> 3;
            int kq  = (f & 7) << 2;
            unsigned h0, l0, h1, l1;
            float4 av = *(const float4*)&A[(size_t)(m0 + row) * K + k0 + kq];
            split2(av.x, av.y, h0, l0);
            split2(av.z, av.w, h1, l1);
            Ahi[row * GS + (kq >> 1)]     = h0;
            Ahi[row * GS + (kq >> 1) + 1] = h1;
            Alo[row * GS + (kq >> 1)]     = l0;
            Alo[row * GS + (kq >> 1) + 1] = l1;
            float4 bv = *(const float4*)&B[(size_t)(n0 + row) * K + k0 + kq];
            split2(bv.x, bv.y, h0, l0);
            split2(bv.z, bv.w, h1, l1);
            Bhi[row * GS + (kq >> 1)]     = h0;
            Bhi[row * GS + (kq >> 1) + 1] = h1;
            Blo[row * GS + (kq >> 1)]     = l0;
            Blo[row * GS + (kq >> 1) + 1] = l1;
        }
        __syncthreads();

#pragma unroll
        for (int kc = 0; kc < 2; kc++) {
            unsigned ah[2][4], al[2][4];
#pragma unroll
            for (int tm = 0; tm < 2; tm++) {
                int r = (wm * 32 + tm * 16 + g) * GS + kc * 8 + c4;
                ah[tm][0] = Ahi[r];
                ah[tm][1] = Ahi[r + 8 * GS];
                ah[tm][2] = Ahi[r + 4];
                ah[tm][3] = Ahi[r + 8 * GS + 4];
                al[tm][0] = Alo[r];
                al[tm][1] = Alo[r + 8 * GS];
                al[tm][2] = Alo[r + 4];
                al[tm][3] = Alo[r + 8 * GS + 4];
            }
#pragma unroll
            for (int tn = 0; tn < 8; tn++) {
                int rb = (wn * 64 + tn * 8 + g) * GS + kc * 8 + c4;
                unsigned bh0 = Bhi[rb],     bh1 = Bhi[rb + 4];
                unsigned bl0 = Blo[rb],     bl1 = Blo[rb + 4];
#pragma unroll
                for (int tm = 0; tm < 2; tm++) {
                    mma_bf16(acc[tm][tn], ah[tm][0], ah[tm][1], ah[tm][2], ah[tm][3], bh0, bh1);
                    mma_bf16(acc[tm][tn], ah[tm][0], ah[tm][1], ah[tm][2], ah[tm][3], bl0, bl1);
                    mma_bf16(acc[tm][tn], al[tm][0], al[tm][1], al[tm][2], al[tm][3], bh0, bh1);
                }
            }
        }
    }

#pragma unroll
    for (int tm = 0; tm < 2; tm++) {
        int r0 = m0 + wm * 32 + tm * 16 + g;
#pragma unroll
        for (int tn = 0; tn < 8; tn++) {
            int col = n0 + wn * 64 + tn * 8 + 2 * c4;
            float2 bb = *(const float2*)&bias[col];
            float* cp0 = &C[(size_t)r0 * N + col];
            float* cp1 = cp0 + 8 * (size_t)N;
            *(float2*)cp0 = make_float2(acc[tm][tn][0] + bb.x, acc[tm][tn][1] + bb.y);
            *(float2*)cp1 = make_float2(acc[tm][tn][2] + bb.x, acc[tm][tn][3] + bb.y);
        }
    }
}

// ---------------------------------------------------------------------------
// One-shot K/V split + V transpose.
// Grid: (N_TOK/64 key-blocks, H_NUM heads). Block: 256 threads.
// K: [key][d] floats -> hi/lo bf16x2 along d -> g_khi/g_klo (coalesced uint2).
// V: [key][d] floats -> smem-transposed -> [d][key] bf16 rows -> g_vt* (uint4).
// ---------------------------------------------------------------------------
#define TROW 36   // u32 row stride of smem transpose tile (144B, 16B-aligned)

__global__ __launch_bounds__(256) void split_kv_kernel()
{
    __shared__ __align__(16) unsigned Th[64 * TROW];
    __shared__ __align__(16) unsigned Tl[64 * TROW];
    __nv_bfloat16* Th_b = reinterpret_cast<__nv_bfloat16*>(Th);
    __nv_bfloat16* Tl_b = reinterpret_cast<__nv_bfloat16*>(Tl);

    const int tid = threadIdx.x;
    const int kb  = blockIdx.x * 64;
    const int h   = blockIdx.y;

#pragma unroll
    for (int i = 0; i < 4; i++) {
        int f   = tid + 256 * i;       // 0..1023 float4 slots (64 keys x 16)
        int key = f >> 4;
        int dq  = (f & 15) << 2;
        const float* kp = &g_qkv[(size_t)(kb + key) * QKV_DIM + C_DIM + h * D_HEAD + dq];
        float4 kv = *(const float4*)kp;
        unsigned h0, l0, h1, l1;
        split2(kv.x, kv.y, h0, l0);
        split2(kv.z, kv.w, h1, l1);
        size_t ko = ((size_t)h * N_TOK + kb + key) * 32 + (dq >> 1);
        *(uint2*)&g_khi[ko] = make_uint2(h0, h1);
        *(uint2*)&g_klo[ko] = make_uint2(l0, l1);
        // V: convert and scatter into smem transpose tile
        float4 vv = *(const float4*)(kp + C_DIM);
        float vals[4] = {vv.x, vv.y, vv.z, vv.w};
#pragma unroll
        for (int j = 0; j < 4; j++) {
            __nv_bfloat16 vh = __float2bfloat16_rn(vals[j]);
            Th_b[(dq + j) * (2 * TROW) + key] = vh;
            Tl_b[(dq + j) * (2 * TROW) + key] =
                __float2bfloat16_rn(vals[j] - __bfloat162float(vh));
        }
    }
    __syncthreads();
    // Write transposed rows out coalesced: thread -> (d, key-chunk).
    // Each d-row of the tile is 32 u32; each thread owns an 8-u32 span = 2 uint4.
    {
        int d = tid >> 2;
        int c = (tid & 3) * 8;
        size_t vo = ((size_t)h * D_HEAD + d) * (N_TOK / 2) + (kb >> 1) + c;
        *(uint4*)&g_vthi[vo]     = *(const uint4*)&Th[d * TROW + c];
        *(uint4*)&g_vthi[vo + 4] = *(const uint4*)&Th[d * TROW + c + 4];
        *(uint4*)&g_vtlo[vo]     = *(const uint4*)&Tl[d * TROW + c];
        *(uint4*)&g_vtlo[vo + 4] = *(const uint4*)&Tl[d * TROW + c + 4];
    }
}

// ---------------------------------------------------------------------------
// Flash attention on tensor cores; K/V staged by pure uint4 copies from the
// pre-split arrays (no conversion in the mainloop).
// Grid: (N/128 q-tiles, 12 heads). Block: 256 threads = 8 warps.
// Quirk: softmax(8 * q.k) — x8 folded into the Q fragments.
// ---------------------------------------------------------------------------
#define BQ 128
#define BK 64
#define KROW 36   // u32 stride per smem row (=> banks 4g+c, all distinct)

__global__ __launch_bounds__(256) void flash_attn_kernel()
{
    __shared__ __align__(16) unsigned Khi[64 * KROW];
    __shared__ __align__(16) unsigned Klo[64 * KROW];
    __shared__ __align__(16) unsigned Vthi[64 * KROW];   // [d][key-pair]
    __shared__ __align__(16) unsigned Vtlo[64 * KROW];

    const int tid  = threadIdx.x;
    const int w    = tid >> 5;
    const int lane = tid & 31;
    const int g    = lane >> 2;        // row-in-tile group 0..7
    const int c4   = lane & 3;         // col pair 0..3
    const int q0   = blockIdx.x * BQ;
    const int h    = blockIdx.y;
    const int hoff = h * D_HEAD;

    // Staging indices (constant over the loop). Each row is 32 u32; each
    // thread owns an 8-u32 span = 2 uint4 per array.
    const int skey = tid >> 2;               // 0..63 (key row / d row)
    const int sc   = (tid & 3) * 8;          // u32 span start
    const size_t kbase = ((size_t)h * N_TOK + skey) * 32 + sc;
    const size_t vbase = ((size_t)h * D_HEAD + skey) * (N_TOK / 2) + sc;
    const int   sdst  = skey * KROW + sc;

    // --- Q fragments (hi/lo), folded x8 scale. 4 k-chunks over d=64. ---
    unsigned qhi[4][4], qlo[4][4];
    {
        const float* qb = g_qkv + (size_t)(q0 + w * 16 + g) * QKV_DIM + hoff;
        const int d0 = 2 * c4;
#pragma unroll
        for (int kc = 0; kc < 4; kc++) {
            float2 x0 = *(const float2*)(qb + 16 * kc + d0);
            float2 x1 = *(const float2*)(qb + 8 * QKV_DIM + 16 * kc + d0);
            float2 x2 = *(const float2*)(qb + 16 * kc + d0 + 8);
            float2 x3 = *(const float2*)(qb + 8 * QKV_DIM + 16 * kc + d0 + 8);
            split2(x0.x * 8.0f, x0.y * 8.0f, qhi[kc][0], qlo[kc][0]);
            split2(x1.x * 8.0f, x1.y * 8.0f, qhi[kc][1], qlo[kc][1]);
            split2(x2.x * 8.0f, x2.y * 8.0f, qhi[kc][2], qlo[kc][2]);
            split2(x3.x * 8.0f, x3.y * 8.0f, qhi[kc][3], qlo[kc][3]);
        }
    }

    float o[8][4];                 // O accumulators: 8 d-tiles x C-frag
    float m0r = -1e30f, m1r = -1e30f, l0r = 0.0f, l1r = 0.0f;
#pragma unroll
    for (int t = 0; t < 8; t++)
#pragma unroll
        for (int j = 0; j < 4; j++) o[t][j] = 0.0f;

    for (int kb = 0; kb < N_TOK; kb += BK) {
        __syncthreads();   // previous iteration's readers done
        // --- Stage K/V: pure uint4 copies (2 per array) from pre-split arrays ---
        {
            size_t ko = kbase + (size_t)kb * 32;
            size_t vo = vbase + (kb >> 1);
            uint4 a0 = *(const uint4*)&g_khi[ko];
            uint4 a1 = *(const uint4*)&g_khi[ko + 4];
            uint4 b0 = *(const uint4*)&g_klo[ko];
            uint4 b1 = *(const uint4*)&g_klo[ko + 4];
            uint4 c0 = *(const uint4*)&g_vthi[vo];
            uint4 c1 = *(const uint4*)&g_vthi[vo + 4];
            uint4 d0 = *(const uint4*)&g_vtlo[vo];
            uint4 d1 = *(const uint4*)&g_vtlo[vo + 4];
            *(uint4*)&Khi[sdst]      = a0;
            *(uint4*)&Khi[sdst + 4]  = a1;
            *(uint4*)&Klo[sdst]      = b0;
            *(uint4*)&Klo[sdst + 4]  = b1;
            *(uint4*)&Vthi[sdst]     = c0;
            *(uint4*)&Vthi[sdst + 4] = c1;
            *(uint4*)&Vtlo[sdst]     = d0;
            *(uint4*)&Vtlo[sdst + 4] = d1;
        }
        __syncthreads();

        // --- S = Q . K^T : 8 n-tiles (8 keys each), 3-term split ---
        float s[8][4];
#pragma unroll
        for (int t = 0; t < 8; t++) {
#pragma unroll
            for (int j = 0; j < 4; j++) s[t][j] = 0.0f;
            const int brow = (t * 8 + g) * KROW;
#pragma unroll
            for (int kc = 0; kc < 4; kc++) {
                unsigned bh0 = Khi[brow + kc * 8 + c4];
                unsigned bh1 = Khi[brow + kc * 8 + c4 + 4];
                unsigned bl0 = Klo[brow + kc * 8 + c4];
                unsigned bl1 = Klo[brow + kc * 8 + c4 + 4];
                mma_bf16(s[t], qhi[kc][0], qhi[kc][1], qhi[kc][2], qhi[kc][3], bh0, bh1);
                mma_bf16(s[t], qhi[kc][0], qhi[kc][1], qhi[kc][2], qhi[kc][3], bl0, bl1);
                mma_bf16(s[t], qlo[kc][0], qlo[kc][1], qlo[kc][2], qlo[kc][3], bh0, bh1);
            }
        }

        // --- Online softmax (rows g and g+8; quad shuffles xor 1,2) ---
        float mx0 = -1e30f, mx1 = -1e30f;
#pragma unroll
        for (int t = 0; t < 8; t++) {
            mx0 = fmaxf(mx0, fmaxf(s[t][0], s[t][1]));
            mx1 = fmaxf(mx1, fmaxf(s[t][2], s[t][3]));
        }
        mx0 = fmaxf(mx0, __shfl_xor_sync(0xffffffffu, mx0, 1));
        mx0 = fmaxf(mx0, __shfl_xor_sync(0xffffffffu, mx0, 2));
        mx1 = fmaxf(mx1, __shfl_xor_sync(0xffffffffu, mx1, 1));
        mx1 = fmaxf(mx1, __shfl_xor_sync(0xffffffffu, mx1, 2));
        float mn0 = fmaxf(m0r, mx0), mn1 = fmaxf(m1r, mx1);
        float cr0 = __expf(m0r - mn0), cr1 = __expf(m1r - mn1);
        m0r = mn0; m1r = mn1;
        float ps0 = 0.0f, ps1 = 0.0f;
#pragma unroll
        for (int t = 0; t < 8; t++) {
            s[t][0] = __expf(s[t][0] - mn0);
            s[t][1] = __expf(s[t][1] - mn0);
            s[t][2] = __expf(s[t][2] - mn1);
            s[t][3] = __expf(s[t][3] - mn1);
            ps0 += s[t][0] + s[t][1];
            ps1 += s[t][2] + s[t][3];
        }
        ps0 += __shfl_xor_sync(0xffffffffu, ps0, 1);
        ps0 += __shfl_xor_sync(0xffffffffu, ps0, 2);
        ps1 += __shfl_xor_sync(0xffffffffu, ps1, 1);
        ps1 += __shfl_xor_sync(0xffffffffu, ps1, 2);
        l0r = l0r * cr0 + ps0;
        l1r = l1r * cr1 + ps1;
#pragma unroll
        for (int t = 0; t < 8; t++) {
            o[t][0] *= cr0; o[t][1] *= cr0;
            o[t][2] *= cr1; o[t][3] *= cr1;
        }

        // --- P fragments (hi/lo) from S C-frags: FA-2 in-register repack ---
        unsigned phi[4][4], plo[4][4];
#pragma unroll
        for (int kc = 0; kc < 4; kc++) {
            split2(s[2 * kc][0],     s[2 * kc][1],     phi[kc][0], plo[kc][0]);
            split2(s[2 * kc][2],     s[2 * kc][3],     phi[kc][1], plo[kc][1]);
            split2(s[2 * kc + 1][0], s[2 * kc + 1][1], phi[kc][2], plo[kc][2]);
            split2(s[2 * kc + 1][2], s[2 * kc + 1][3], phi[kc][3], plo[kc][3]);
        }

        // --- O += P . V : 8 d-tiles, 3-term split ---
#pragma unroll
        for (int t = 0; t < 8; t++) {
            const int brow = (t * 8 + g) * KROW;
#pragma unroll
            for (int kc = 0; kc < 4; kc++) {
                unsigned bh0 = Vthi[brow + kc * 8 + c4];
                unsigned bh1 = Vthi[brow + kc * 8 + c4 + 4];
                unsigned bl0 = Vtlo[brow + kc * 8 + c4];
                unsigned bl1 = Vtlo[brow + kc * 8 + c4 + 4];
                mma_bf16(o[t], phi[kc][0], phi[kc][1], phi[kc][2], phi[kc][3], bh0, bh1);
                mma_bf16(o[t], phi[kc][0], phi[kc][1], phi[kc][2], phi[kc][3], bl0, bl1);
                mma_bf16(o[t], plo[kc][0], plo[kc][1], plo[kc][2], plo[kc][3], bh0, bh1);
            }
        }
    }

    // --- Normalize, write O to g_o[n][h*64+d] ---
    float inv0 = 1.0f / l0r, inv1 = 1.0f / l1r;
    float* op0 = g_o + (size_t)(q0 + w * 16 + g) * C_DIM + hoff;
    float* op1 = op0 + 8 * C_DIM;
#pragma unroll
    for (int t = 0; t < 8; t++) {
        *(float2*)(op0 + t * 8 + 2 * c4) = make_float2(o[t][0] * inv0, o[t][1] * inv0);
        *(float2*)(op1 + t * 8 + 2 * c4) = make_float2(o[t][2] * inv1, o[t][3] * inv1);
    }
}

// ---------------------------------------------------------------------------
// Launch: qkv GEMM -> K/V split -> flash attention -> proj GEMM
// ---------------------------------------------------------------------------
extern "C" void kernel_launch(void* const* d_in, const int* in_sizes, int n_in,
                              void* d_out, int out_size)
{
    (void)in_sizes; (void)n_in; (void)out_size;
    const float* x      = (const float*)d_in[0];
    const float* qkv_w  = (const float*)d_in[1];
    const float* qkv_b  = (const float*)d_in[2];
    const float* proj_w = (const float*)d_in[3];
    const float* proj_b = (const float*)d_in[4];
    float* out = (float*)d_out;

    float* qkv_ptr = nullptr;
    float* o_ptr   = nullptr;
    cudaGetSymbolAddress((void**)&qkv_ptr, g_qkv);
    cudaGetSymbolAddress((void**)&o_ptr,   g_o);

    // 1) qkv[4096,2304] = x[4096,768] @ qkv_w[2304,768]^T + qkv_b
    {
        dim3 grid(QKV_DIM / 128, N_TOK / 128);
        gemm_bf16s_nt_bias<<<grid, 256>>>(x, qkv_w, qkv_b, qkv_ptr,
                                          N_TOK, QKV_DIM, C_DIM);
    }
    // 2) one-shot K/V Dekker split + V transpose
    {
        dim3 grid(N_TOK / 64, H_NUM);
        split_kv_kernel<<<grid, 256>>>();
    }
    // 3) flash attention (tensor cores) -> g_o[4096,768]
    {
        dim3 grid(N_TOK / BQ, H_NUM);
        flash_attn_kernel<<<grid, 256>>>();
    }
    // 4) out[4096,768] = g_o @ proj_w[768,768]^T + proj_b
    {
        dim3 grid(C_DIM / 128, N_TOK / 128);
        gemm_bf16s_nt_bias<<<grid, 256>>>(o_ptr, proj_w, proj_b, out,
                                          N_TOK, C_DIM, C_DIM);
    }
}